// round 9
// baseline (speedup 1.0000x reference)
#include <cuda_runtime.h>
#include <cuda_bf16.h>
#include <cstdint>

static constexpr int Sc = 2048, Dc = 64;

// fragment buffers (layout unchanged):
// Q: ((bh*128+blk)*2+sp)*4+ks -> [lane] uint4(a0,a1,a2,a3)
// K: ((bh*256+cbg)*2+sp)*2+kp -> [lane] uint4(ks_even b0,b1, ks_odd b0,b1)
__device__ uint4 g_qfrag[64 * 128 * 2 * 4 * 32];
__device__ uint4 g_kfrag[64 * 256 * 2 * 2 * 32];

__device__ __forceinline__ void threefry2x32(uint32_t c0, uint32_t c1,
                                             uint32_t& o0, uint32_t& o1)
{
    const uint32_t K0 = 0u, K1 = 42u, K2 = 0x1BD11BDAu ^ K0 ^ K1;
    uint32_t x0 = c0 + K0, x1 = c1 + K1;
#define TF_R(r) { x0 += x1; x1 = __funnelshift_l(x1, x1, (r)); x1 ^= x0; }
    TF_R(13) TF_R(15) TF_R(26) TF_R(6)  x0 += K1; x1 += K2 + 1u;
    TF_R(17) TF_R(29) TF_R(16) TF_R(24) x0 += K2; x1 += K0 + 2u;
    TF_R(13) TF_R(15) TF_R(26) TF_R(6)  x0 += K0; x1 += K1 + 3u;
    TF_R(17) TF_R(29) TF_R(16) TF_R(24) x0 += K1; x1 += K2 + 4u;
    TF_R(13) TF_R(15) TF_R(26) TF_R(6)  x0 += K2; x1 += K0 + 5u;
#undef TF_R
    o0 = x0; o1 = x1;
}
__device__ __forceinline__ bool keep_mask(uint32_t bh, uint32_t gq, uint32_t gk)
{
    uint32_t i = (bh << 22) | (gq << 11) | gk, b0, b1;
    threefry2x32(0u, i, b0, b1);
    return ((b0 ^ b1) >> 9) < 838861u;
}

__device__ __forceinline__ uint32_t pk_bf16(float lo, float hi)
{ uint32_t r; asm("cvt.rn.bf16x2.f32 %0, %1, %2;" : "=r"(r) : "f"(hi), "f"(lo)); return r; }

__device__ __forceinline__ uint32_t pk_split(float x, float y, int sp)
{
    float xh = __bfloat162float(__float2bfloat16(x));
    float yh = __bfloat162float(__float2bfloat16(y));
    return sp ? pk_bf16(x - xh, y - yh) : pk_bf16(xh, yh);
}

__device__ __forceinline__ void mma16816(float* c,
                                         uint4 a, uint32_t b0, uint32_t b1)
{
    asm volatile("mma.sync.aligned.m16n8k16.row.col.f32.bf16.bf16.f32 "
                 "{%0,%1,%2,%3}, {%4,%5,%6,%7}, {%8,%9}, {%0,%1,%2,%3};"
                 : "+f"(c[0]), "+f"(c[1]), "+f"(c[2]), "+f"(c[3])
                 : "r"(a.x), "r"(a.y), "r"(a.z), "r"(a.w), "r"(b0), "r"(b1));
}

// ---------------- pre-pass (unchanged) ---------------------------------------
__global__ void __launch_bounds__(256)
prepass_kernel(const float* __restrict__ q, const float* __restrict__ k)
{
    int gw = (blockIdx.x * 256 + threadIdx.x) >> 5;
    int lane = threadIdx.x & 31;
    if (gw < 64 * 128 * 2 * 4) {
        int ks = gw & 3, sp = (gw >> 2) & 1, blk = (gw >> 3) & 127, bh = gw >> 10;
        int r0 = blk * 16 + (lane >> 2);
        int kb = ks * 16 + (lane & 3) * 2;
        const float* qb = q + ((size_t)bh * Sc) * Dc;
        float2 p00 = *(const float2*)(qb + (size_t)r0 * Dc + kb);
        float2 p10 = *(const float2*)(qb + (size_t)(r0 + 8) * Dc + kb);
        float2 p01 = *(const float2*)(qb + (size_t)r0 * Dc + kb + 8);
        float2 p11 = *(const float2*)(qb + (size_t)(r0 + 8) * Dc + kb + 8);
        uint4 o;
        o.x = pk_split(p00.x * 8.f, p00.y * 8.f, sp);
        o.y = pk_split(p10.x * 8.f, p10.y * 8.f, sp);
        o.z = pk_split(p01.x * 8.f, p01.y * 8.f, sp);
        o.w = pk_split(p11.x * 8.f, p11.y * 8.f, sp);
        g_qfrag[(size_t)gw * 32 + lane] = o;
    } else {
        int w2 = gw - 64 * 128 * 2 * 4;
        int kp = w2 & 1, sp = (w2 >> 1) & 1, cbg = (w2 >> 2) & 255, bh = w2 >> 10;
        int n = cbg * 8 + (lane >> 2);
        const float* kr = k + ((size_t)bh * Sc + n) * Dc;
        uint4 o;
        int k0 = (kp * 2) * 16 + (lane & 3) * 2;
        o.x = pk_split(kr[k0], kr[k0 + 1], sp);
        o.y = pk_split(kr[k0 + 8], kr[k0 + 9], sp);
        int k1 = (kp * 2 + 1) * 16 + (lane & 3) * 2;
        o.z = pk_split(kr[k1], kr[k1 + 1], sp);
        o.w = pk_split(kr[k1 + 8], kr[k1 + 9], sp);
        g_kfrag[(size_t)w2 * 32 + lane] = o;
    }
}

// ---------------- main attention kernel --------------------------------------
__global__ void __launch_bounds__(128, 4)
attn_main(const float* __restrict__ gv, float* __restrict__ gout)
{
    __shared__ uint4 sK4[2048];   // 32 KB: one K-frag tile
    const int tid = threadIdx.x, w = tid >> 5, lane = tid & 31;
    const uint32_t bh = blockIdx.y;
    const int q0 = blockIdx.x * 64;
    const int blk = blockIdx.x * 4 + w;

    // A hi-split fragments held in regs; lo-split fetched lazily from L2
    uint4 AH[4];
    const uint4* qf = g_qfrag + ((size_t)(bh * 128 + blk) * 2) * 4 * 32;
#pragma unroll
    for (int ks = 0; ks < 4; ++ks) AH[ks] = qf[ks * 32 + lane];

    float O[2][16];
#pragma unroll
    for (int r = 0; r < 2; ++r)
#pragma unroll
        for (int c = 0; c < 16; ++c) O[r][c] = 0.f;
    float m0 = -1e30f, m1 = -1e30f, l0 = 0.f, l1 = 0.f;

    const uint32_t gq0 = (uint32_t)(q0 + w * 16 + (lane >> 2));
    const float* vb = gv + (size_t)bh * Sc * Dc;

    for (int kt = 0; kt < 16; ++kt) {
        __syncthreads();
        {
            const uint4* kf = g_kfrag + (size_t)(bh * 16 + kt) * 2048;
#pragma unroll
            for (int i = 0; i < 16; ++i)
                sK4[tid + 128 * i] = kf[tid + 128 * i];
        }
        __syncthreads();

#pragma unroll 1
        for (int half = 0; half < 2; ++half) {
            // ---- speculative hi-only pass: 8 independent 4-MMA chains ----
            float C[8][4];
#pragma unroll
            for (int cb = 0; cb < 8; ++cb) {
                C[cb][0] = C[cb][1] = C[cb][2] = C[cb][3] = 0.f;
                const int cbg = half * 8 + cb;
                uint4 Bh0 = sK4[(cbg * 4 + 0) * 32 + lane];
                uint4 Bh1 = sK4[(cbg * 4 + 1) * 32 + lane];
                mma16816(C[cb], AH[0], Bh0.x, Bh0.y);
                mma16816(C[cb], AH[1], Bh0.z, Bh0.w);
                mma16816(C[cb], AH[2], Bh1.x, Bh1.y);
                mma16816(C[cb], AH[3], Bh1.z, Bh1.w);
            }

            // ---- cheap significance gate (hi error <= ~0.8 -> window 30) ----
            float rm0 = -1e30f, rm1 = -1e30f;
#pragma unroll
            for (int cb = 0; cb < 8; ++cb) {
                rm0 = fmaxf(rm0, fmaxf(C[cb][0], C[cb][1]));
                rm1 = fmaxf(rm1, fmaxf(C[cb][2], C[cb][3]));
            }
            rm0 = fmaxf(rm0, __shfl_xor_sync(0xffffffffu, rm0, 1));
            rm0 = fmaxf(rm0, __shfl_xor_sync(0xffffffffu, rm0, 2));
            rm1 = fmaxf(rm1, __shfl_xor_sync(0xffffffffu, rm1, 1));
            rm1 = fmaxf(rm1, __shfl_xor_sync(0xffffffffu, rm1, 2));
            bool sig = (rm0 > m0 - 30.f) | (rm1 > m1 - 30.f);
            if (!__any_sync(0xffffffffu, sig)) continue;

            // ---- rare path: apply corrections QlKh + QhKl, then exact softmax
            uint4 AL[4];
#pragma unroll
            for (int ks = 0; ks < 4; ++ks) AL[ks] = qf[(4 + ks) * 32 + lane];
#pragma unroll
            for (int cb = 0; cb < 8; ++cb) {
                const int cbg = half * 8 + cb;
                uint4 Bh0 = sK4[(cbg * 4 + 0) * 32 + lane];
                uint4 Bh1 = sK4[(cbg * 4 + 1) * 32 + lane];
                uint4 Bl0 = sK4[(cbg * 4 + 2) * 32 + lane];
                uint4 Bl1 = sK4[(cbg * 4 + 3) * 32 + lane];
                mma16816(C[cb], AL[0], Bh0.x, Bh0.y);
                mma16816(C[cb], AL[1], Bh0.z, Bh0.w);
                mma16816(C[cb], AL[2], Bh1.x, Bh1.y);
                mma16816(C[cb], AL[3], Bh1.z, Bh1.w);
                mma16816(C[cb], AH[0], Bl0.x, Bl0.y);
                mma16816(C[cb], AH[1], Bl0.z, Bl0.w);
                mma16816(C[cb], AH[2], Bl1.x, Bl1.y);
                mma16816(C[cb], AH[3], Bl1.z, Bl1.w);
            }

            // precise row maxima over corrected C
            rm0 = -1e30f; rm1 = -1e30f;
#pragma unroll
            for (int cb = 0; cb < 8; ++cb) {
                rm0 = fmaxf(rm0, fmaxf(C[cb][0], C[cb][1]));
                rm1 = fmaxf(rm1, fmaxf(C[cb][2], C[cb][3]));
            }
            rm0 = fmaxf(rm0, __shfl_xor_sync(0xffffffffu, rm0, 1));
            rm0 = fmaxf(rm0, __shfl_xor_sync(0xffffffffu, rm0, 2));
            rm1 = fmaxf(rm1, __shfl_xor_sync(0xffffffffu, rm1, 1));
            rm1 = fmaxf(rm1, __shfl_xor_sync(0xffffffffu, rm1, 2));

            float mn0 = fmaxf(m0, rm0), mn1 = fmaxf(m1, rm1);
            float al0 = __expf(m0 - mn0), al1 = __expf(m1 - mn1);
            l0 *= al0; l1 *= al1;
#pragma unroll
            for (int c = 0; c < 16; ++c) { O[0][c] *= al0; O[1][c] *= al1; }
            m0 = mn0; m1 = mn1;

#pragma unroll 1
            for (int cb = 0; cb < 8; ++cb) {
                float e0 = __expf(C[cb][0] - m0);
                float e1 = __expf(C[cb][1] - m0);
                float e2 = __expf(C[cb][2] - m1);
                float e3 = __expf(C[cb][3] - m1);
                l0 += e0 + e1; l1 += e2 + e3;

                const int gk0 = kt * 128 + (half * 8 + cb) * 8 + (lane & 3) * 2;
                bool sv[4] = {false, false, false, false};
                float p10[4];
                if (e0 > 1e-12f && keep_mask(bh, gq0, gk0))         { sv[0] = true; p10[0] = e0 * 10.f; }
                if (e1 > 1e-12f && keep_mask(bh, gq0, gk0 + 1))     { sv[1] = true; p10[1] = e1 * 10.f; }
                if (e2 > 1e-12f && keep_mask(bh, gq0 + 8, gk0))     { sv[2] = true; p10[2] = e2 * 10.f; }
                if (e3 > 1e-12f && keep_mask(bh, gq0 + 8, gk0 + 1)) { sv[3] = true; p10[3] = e3 * 10.f; }

                if (__ballot_sync(0xffffffffu, sv[0] | sv[1] | sv[2] | sv[3])) {
#pragma unroll
                    for (int pos = 0; pos < 4; ++pos) {
                        unsigned mk = __ballot_sync(0xffffffffu, sv[pos]);
                        while (mk) {
                            int src = __ffs(mk) - 1;
                            mk &= mk - 1;
                            int gkb  = __shfl_sync(0xffffffffu, gk0 + (pos & 1), src);
                            float pb = __shfl_sync(0xffffffffu, p10[pos], src);
                            if ((lane >> 2) == (src >> 2)) {
                                const float* vc = vb + (size_t)gkb * Dc + (lane & 3) * 16;
                                float* Or = O[pos >> 1];
#pragma unroll
                                for (int c = 0; c < 4; ++c) {
                                    float4 vv = *(const float4*)(vc + 4 * c);
                                    Or[4 * c + 0] = fmaf(pb, vv.x, Or[4 * c + 0]);
                                    Or[4 * c + 1] = fmaf(pb, vv.y, Or[4 * c + 1]);
                                    Or[4 * c + 2] = fmaf(pb, vv.z, Or[4 * c + 2]);
                                    Or[4 * c + 3] = fmaf(pb, vv.w, Or[4 * c + 3]);
                                }
                            }
                        }
                    }
                }
            }
        }
    }

    // ---- epilogue ----
    l0 += __shfl_xor_sync(0xffffffffu, l0, 1);
    l0 += __shfl_xor_sync(0xffffffffu, l0, 2);
    l1 += __shfl_xor_sync(0xffffffffu, l1, 1);
    l1 += __shfl_xor_sync(0xffffffffu, l1, 2);
    float il0 = 1.0f / l0, il1 = 1.0f / l1;

    const int gr0 = q0 + w * 16 + (lane >> 2);
    float* o0 = gout + ((size_t)bh * Sc + gr0) * Dc + (lane & 3) * 16;
    float* o1 = gout + ((size_t)bh * Sc + gr0 + 8) * Dc + (lane & 3) * 16;
#pragma unroll
    for (int c = 0; c < 4; ++c) {
        *(float4*)(o0 + 4 * c) = make_float4(O[0][4*c] * il0, O[0][4*c+1] * il0,
                                             O[0][4*c+2] * il0, O[0][4*c+3] * il0);
        *(float4*)(o1 + 4 * c) = make_float4(O[1][4*c] * il1, O[1][4*c+1] * il1,
                                             O[1][4*c+2] * il1, O[1][4*c+3] * il1);
    }
}

extern "C" void kernel_launch(void* const* d_in, const int* in_sizes, int n_in,
                              void* d_out, int out_size)
{
    (void)in_sizes; (void)n_in; (void)out_size;
    const float* q = (const float*)d_in[0];
    const float* k = (const float*)d_in[1];
    const float* v = (const float*)d_in[2];
    float* o = (float*)d_out;

    prepass_kernel<<<16384, 256>>>(q, k);
    dim3 grid(Sc / 64, 64);
    attn_main<<<grid, 128>>>(v, o);
}

// round 10
// speedup vs baseline: 1.4222x; 1.4222x over previous
#include <cuda_runtime.h>
#include <cuda_bf16.h>
#include <cstdint>

static constexpr int Sc = 2048, Dc = 64;

// fragment buffers:
// Q: ((bh*128+blk)*2+sp)*4+ks -> [lane] uint4(a0,a1,a2,a3)
// K: ((bh*256+cbg)*2+sp)*2+kp -> [lane] uint4(ks_even b0,b1, ks_odd b0,b1)
__device__ uint4 g_qfrag[64 * 128 * 2 * 4 * 32];
__device__ uint4 g_kfrag[64 * 256 * 2 * 2 * 32];

__device__ __forceinline__ void threefry2x32(uint32_t c0, uint32_t c1,
                                             uint32_t& o0, uint32_t& o1)
{
    const uint32_t K0 = 0u, K1 = 42u, K2 = 0x1BD11BDAu ^ K0 ^ K1;
    uint32_t x0 = c0 + K0, x1 = c1 + K1;
#define TF_R(r) { x0 += x1; x1 = __funnelshift_l(x1, x1, (r)); x1 ^= x0; }
    TF_R(13) TF_R(15) TF_R(26) TF_R(6)  x0 += K1; x1 += K2 + 1u;
    TF_R(17) TF_R(29) TF_R(16) TF_R(24) x0 += K2; x1 += K0 + 2u;
    TF_R(13) TF_R(15) TF_R(26) TF_R(6)  x0 += K0; x1 += K1 + 3u;
    TF_R(17) TF_R(29) TF_R(16) TF_R(24) x0 += K1; x1 += K2 + 4u;
    TF_R(13) TF_R(15) TF_R(26) TF_R(6)  x0 += K2; x1 += K0 + 5u;
#undef TF_R
    o0 = x0; o1 = x1;
}
__device__ __forceinline__ bool keep_mask(uint32_t bh, uint32_t gq, uint32_t gk)
{
    uint32_t i = (bh << 22) | (gq << 11) | gk, b0, b1;
    threefry2x32(0u, i, b0, b1);
    return ((b0 ^ b1) >> 9) < 838861u;
}

__device__ __forceinline__ uint32_t pk_bf16(float lo, float hi)
{ uint32_t r; asm("cvt.rn.bf16x2.f32 %0, %1, %2;" : "=r"(r) : "f"(hi), "f"(lo)); return r; }

__device__ __forceinline__ uint32_t pk_split(float x, float y, int sp)
{
    float xh = __bfloat162float(__float2bfloat16(x));
    float yh = __bfloat162float(__float2bfloat16(y));
    return sp ? pk_bf16(x - xh, y - yh) : pk_bf16(xh, yh);
}

__device__ __forceinline__ void mma16816(float& c0, float& c1, float& c2, float& c3,
                                         uint32_t a0, uint32_t a1, uint32_t a2, uint32_t a3,
                                         uint32_t b0, uint32_t b1)
{
    asm volatile("mma.sync.aligned.m16n8k16.row.col.f32.bf16.bf16.f32 "
                 "{%0,%1,%2,%3}, {%4,%5,%6,%7}, {%8,%9}, {%0,%1,%2,%3};"
                 : "+f"(c0), "+f"(c1), "+f"(c2), "+f"(c3)
                 : "r"(a0), "r"(a1), "r"(a2), "r"(a3), "r"(b0), "r"(b1));
}

// ---------------- pre-pass (unchanged) ---------------------------------------
__global__ void __launch_bounds__(256)
prepass_kernel(const float* __restrict__ q, const float* __restrict__ k)
{
    int gw = (blockIdx.x * 256 + threadIdx.x) >> 5;
    int lane = threadIdx.x & 31;
    if (gw < 64 * 128 * 2 * 4) {
        int ks = gw & 3, sp = (gw >> 2) & 1, blk = (gw >> 3) & 127, bh = gw >> 10;
        int r0 = blk * 16 + (lane >> 2);
        int kb = ks * 16 + (lane & 3) * 2;
        const float* qb = q + ((size_t)bh * Sc) * Dc;
        float2 p00 = *(const float2*)(qb + (size_t)r0 * Dc + kb);
        float2 p10 = *(const float2*)(qb + (size_t)(r0 + 8) * Dc + kb);
        float2 p01 = *(const float2*)(qb + (size_t)r0 * Dc + kb + 8);
        float2 p11 = *(const float2*)(qb + (size_t)(r0 + 8) * Dc + kb + 8);
        uint4 o;
        o.x = pk_split(p00.x * 8.f, p00.y * 8.f, sp);
        o.y = pk_split(p10.x * 8.f, p10.y * 8.f, sp);
        o.z = pk_split(p01.x * 8.f, p01.y * 8.f, sp);
        o.w = pk_split(p11.x * 8.f, p11.y * 8.f, sp);
        g_qfrag[(size_t)gw * 32 + lane] = o;
    } else {
        int w2 = gw - 64 * 128 * 2 * 4;
        int kp = w2 & 1, sp = (w2 >> 1) & 1, cbg = (w2 >> 2) & 255, bh = w2 >> 10;
        int n = cbg * 8 + (lane >> 2);
        const float* kr = k + ((size_t)bh * Sc + n) * Dc;
        uint4 o;
        int k0 = (kp * 2) * 16 + (lane & 3) * 2;
        o.x = pk_split(kr[k0], kr[k0 + 1], sp);
        o.y = pk_split(kr[k0 + 8], kr[k0 + 9], sp);
        int k1 = (kp * 2 + 1) * 16 + (lane & 3) * 2;
        o.z = pk_split(kr[k1], kr[k1 + 1], sp);
        o.w = pk_split(kr[k1 + 8], kr[k1 + 9], sp);
        g_kfrag[(size_t)w2 * 32 + lane] = o;
    }
}

// ---------------- main attention kernel (R7 shape, reg-neutral tweaks) ------
__global__ void __launch_bounds__(256, 2)
attn_main(const float* __restrict__ gv, float* __restrict__ gout)
{
    __shared__ uint4 sK4[2048];   // 32 KB: one K-frag tile
    const int tid = threadIdx.x, w = tid >> 5, lane = tid & 31;
    const uint32_t bh = blockIdx.y;
    const int q0 = blockIdx.x * 128;
    const int blk = blockIdx.x * 8 + w;

    uint4 A[2][4];
    {
        const uint4* qf = g_qfrag + ((size_t)(bh * 128 + blk) * 2) * 4 * 32;
#pragma unroll
        for (int sp = 0; sp < 2; ++sp)
#pragma unroll
            for (int ks = 0; ks < 4; ++ks)
                A[sp][ks] = qf[(sp * 4 + ks) * 32 + lane];
    }

    float O[2][16];
#pragma unroll
    for (int r = 0; r < 2; ++r)
#pragma unroll
        for (int c = 0; c < 16; ++c) O[r][c] = 0.f;
    float m0 = -1e30f, m1 = -1e30f, l0 = 0.f, l1 = 0.f;

    const uint32_t gq0 = (uint32_t)(q0 + w * 16 + (lane >> 2));
    const float* vb = gv + (size_t)bh * Sc * Dc;

    for (int kt = 0; kt < 16; ++kt) {
        __syncthreads();
        {
            const uint4* kf = g_kfrag + (size_t)(bh * 16 + kt) * 2048;
#pragma unroll
            for (int i = 0; i < 8; ++i)
                sK4[tid + 256 * i] = kf[tid + 256 * i];
        }
        __syncthreads();

#pragma unroll 1
        for (int cb = 0; cb < 16; ++cb) {
            uint4 B[2][2];
#pragma unroll
            for (int sb = 0; sb < 2; ++sb)
#pragma unroll
                for (int kp = 0; kp < 2; ++kp)
                    B[sb][kp] = sK4[((cb * 2 + sb) * 2 + kp) * 32 + lane];

            // ---- 3 split products: QhKh + QlKh + QhKl (QlKl dropped) ----
            float c0 = 0.f, c1 = 0.f, c2 = 0.f, c3 = 0.f;
#pragma unroll
            for (int ks = 0; ks < 4; ++ks) {
                uint32_t hb0 = (ks & 1) ? B[0][ks >> 1].z : B[0][ks >> 1].x;
                uint32_t hb1 = (ks & 1) ? B[0][ks >> 1].w : B[0][ks >> 1].y;
                mma16816(c0, c1, c2, c3,
                         A[0][ks].x, A[0][ks].y, A[0][ks].z, A[0][ks].w, hb0, hb1);
                mma16816(c0, c1, c2, c3,
                         A[1][ks].x, A[1][ks].y, A[1][ks].z, A[1][ks].w, hb0, hb1);
                uint32_t lb0 = (ks & 1) ? B[1][ks >> 1].z : B[1][ks >> 1].x;
                uint32_t lb1 = (ks & 1) ? B[1][ks >> 1].w : B[1][ks >> 1].y;
                mma16816(c0, c1, c2, c3,
                         A[0][ks].x, A[0][ks].y, A[0][ks].z, A[0][ks].w, lb0, lb1);
            }

            // ---- cheap combined gate: 3 FMNMX + 2 shuffles + 1 vote ----
            float bm = fmaxf(fmaxf(c0, c1), fmaxf(c2, c3));
            bm = fmaxf(bm, __shfl_xor_sync(0xffffffffu, bm, 1));
            bm = fmaxf(bm, __shfl_xor_sync(0xffffffffu, bm, 2));
            bool sig = bm > fminf(m0, m1) - 28.f;
            if (!__any_sync(0xffffffffu, sig)) continue;

            // ---- slow path (rare): precise row maxima, softmax, dropout ----
            float rm0 = fmaxf(c0, c1), rm1 = fmaxf(c2, c3);
            rm0 = fmaxf(rm0, __shfl_xor_sync(0xffffffffu, rm0, 1));
            rm0 = fmaxf(rm0, __shfl_xor_sync(0xffffffffu, rm0, 2));
            rm1 = fmaxf(rm1, __shfl_xor_sync(0xffffffffu, rm1, 1));
            rm1 = fmaxf(rm1, __shfl_xor_sync(0xffffffffu, rm1, 2));

            bool sv[4] = {false, false, false, false};
            float p10[4] = {0.f, 0.f, 0.f, 0.f};
            const int gk0 = kt * 128 + cb * 8 + (lane & 3) * 2;

            if (rm0 > m0 - 28.f) {
                float mn = fmaxf(m0, rm0);
                if (mn > m0) {
                    float al = __expf(m0 - mn);
                    l0 *= al;
#pragma unroll
                    for (int c = 0; c < 16; ++c) O[0][c] *= al;
                    m0 = mn;
                }
                float e0 = (c0 > mn - 28.f) ? __expf(c0 - mn) : 0.f;
                float e1 = (c1 > mn - 28.f) ? __expf(c1 - mn) : 0.f;
                l0 += e0 + e1;
                if (e0 > 1e-12f && keep_mask(bh, gq0, gk0))     { sv[0] = true; p10[0] = e0 * 10.f; }
                if (e1 > 1e-12f && keep_mask(bh, gq0, gk0 + 1)) { sv[1] = true; p10[1] = e1 * 10.f; }
            }
            if (rm1 > m1 - 28.f) {
                float mn = fmaxf(m1, rm1);
                if (mn > m1) {
                    float al = __expf(m1 - mn);
                    l1 *= al;
#pragma unroll
                    for (int c = 0; c < 16; ++c) O[1][c] *= al;
                    m1 = mn;
                }
                float e2 = (c2 > mn - 28.f) ? __expf(c2 - mn) : 0.f;
                float e3 = (c3 > mn - 28.f) ? __expf(c3 - mn) : 0.f;
                l1 += e2 + e3;
                if (e2 > 1e-12f && keep_mask(bh, gq0 + 8, gk0))     { sv[2] = true; p10[2] = e2 * 10.f; }
                if (e3 > 1e-12f && keep_mask(bh, gq0 + 8, gk0 + 1)) { sv[3] = true; p10[3] = e3 * 10.f; }
            }

            if (__ballot_sync(0xffffffffu, sv[0] | sv[1] | sv[2] | sv[3])) {
#pragma unroll
                for (int pos = 0; pos < 4; ++pos) {
                    unsigned mk = __ballot_sync(0xffffffffu, sv[pos]);
                    while (mk) {
                        int src = __ffs(mk) - 1;
                        mk &= mk - 1;
                        int gkb  = __shfl_sync(0xffffffffu, gk0 + (pos & 1), src);
                        float pb = __shfl_sync(0xffffffffu, p10[pos], src);
                        if ((lane >> 2) == (src >> 2)) {
                            const float* vc = vb + (size_t)gkb * Dc + (lane & 3) * 16;
                            float* Or = O[pos >> 1];
#pragma unroll
                            for (int c = 0; c < 4; ++c) {
                                float4 vv = *(const float4*)(vc + 4 * c);
                                Or[4 * c + 0] = fmaf(pb, vv.x, Or[4 * c + 0]);
                                Or[4 * c + 1] = fmaf(pb, vv.y, Or[4 * c + 1]);
                                Or[4 * c + 2] = fmaf(pb, vv.z, Or[4 * c + 2]);
                                Or[4 * c + 3] = fmaf(pb, vv.w, Or[4 * c + 3]);
                            }
                        }
                    }
                }
            }
        }
    }

    // ---- epilogue ----
    l0 += __shfl_xor_sync(0xffffffffu, l0, 1);
    l0 += __shfl_xor_sync(0xffffffffu, l0, 2);
    l1 += __shfl_xor_sync(0xffffffffu, l1, 1);
    l1 += __shfl_xor_sync(0xffffffffu, l1, 2);
    float il0 = 1.0f / l0, il1 = 1.0f / l1;

    const int gr0 = q0 + w * 16 + (lane >> 2);
    float* o0 = gout + ((size_t)bh * Sc + gr0) * Dc + (lane & 3) * 16;
    float* o1 = gout + ((size_t)bh * Sc + gr0 + 8) * Dc + (lane & 3) * 16;
#pragma unroll
    for (int c = 0; c < 4; ++c) {
        *(float4*)(o0 + 4 * c) = make_float4(O[0][4*c] * il0, O[0][4*c+1] * il0,
                                             O[0][4*c+2] * il0, O[0][4*c+3] * il0);
        *(float4*)(o1 + 4 * c) = make_float4(O[1][4*c] * il1, O[1][4*c+1] * il1,
                                             O[1][4*c+2] * il1, O[1][4*c+3] * il1);
    }
}

extern "C" void kernel_launch(void* const* d_in, const int* in_sizes, int n_in,
                              void* d_out, int out_size)
{
    (void)in_sizes; (void)n_in; (void)out_size;
    const float* q = (const float*)d_in[0];
    const float* k = (const float*)d_in[1];
    const float* v = (const float*)d_in[2];
    float* o = (float*)d_out;

    prepass_kernel<<<16384, 256>>>(q, k);
    dim3 grid(Sc / 128, 64);
    attn_main<<<grid, 256>>>(v, o);
}

// round 11
// speedup vs baseline: 1.4753x; 1.0373x over previous
#include <cuda_runtime.h>
#include <cuda_bf16.h>
#include <cstdint>

static constexpr int Sc = 2048, Dc = 64;

// fragment buffers:
// Q: ((bh*128+blk)*2+sp)*4+ks -> [lane] uint4(a0,a1,a2,a3)
// K: ((bh*256+cbg)*2+sp)*2+kp -> [lane] uint4(ks_even b0,b1, ks_odd b0,b1)
__device__ uint4 g_qfrag[64 * 128 * 2 * 4 * 32];
__device__ uint4 g_kfrag[64 * 256 * 2 * 2 * 32];

__device__ __forceinline__ void threefry2x32(uint32_t c0, uint32_t c1,
                                             uint32_t& o0, uint32_t& o1)
{
    const uint32_t K0 = 0u, K1 = 42u, K2 = 0x1BD11BDAu ^ K0 ^ K1;
    uint32_t x0 = c0 + K0, x1 = c1 + K1;
#define TF_R(r) { x0 += x1; x1 = __funnelshift_l(x1, x1, (r)); x1 ^= x0; }
    TF_R(13) TF_R(15) TF_R(26) TF_R(6)  x0 += K1; x1 += K2 + 1u;
    TF_R(17) TF_R(29) TF_R(16) TF_R(24) x0 += K2; x1 += K0 + 2u;
    TF_R(13) TF_R(15) TF_R(26) TF_R(6)  x0 += K0; x1 += K1 + 3u;
    TF_R(17) TF_R(29) TF_R(16) TF_R(24) x0 += K1; x1 += K2 + 4u;
    TF_R(13) TF_R(15) TF_R(26) TF_R(6)  x0 += K2; x1 += K0 + 5u;
#undef TF_R
    o0 = x0; o1 = x1;
}
__device__ __forceinline__ bool keep_mask(uint32_t bh, uint32_t gq, uint32_t gk)
{
    uint32_t i = (bh << 22) | (gq << 11) | gk, b0, b1;
    threefry2x32(0u, i, b0, b1);
    return ((b0 ^ b1) >> 9) < 838861u;
}

__device__ __forceinline__ uint32_t pk_bf16(float lo, float hi)
{ uint32_t r; asm("cvt.rn.bf16x2.f32 %0, %1, %2;" : "=r"(r) : "f"(hi), "f"(lo)); return r; }

__device__ __forceinline__ uint32_t pk_split(float x, float y, int sp)
{
    float xh = __bfloat162float(__float2bfloat16(x));
    float yh = __bfloat162float(__float2bfloat16(y));
    return sp ? pk_bf16(x - xh, y - yh) : pk_bf16(xh, yh);
}

__device__ __forceinline__ void mma16816(float& c0, float& c1, float& c2, float& c3,
                                         uint32_t a0, uint32_t a1, uint32_t a2, uint32_t a3,
                                         uint32_t b0, uint32_t b1)
{
    asm volatile("mma.sync.aligned.m16n8k16.row.col.f32.bf16.bf16.f32 "
                 "{%0,%1,%2,%3}, {%4,%5,%6,%7}, {%8,%9}, {%0,%1,%2,%3};"
                 : "+f"(c0), "+f"(c1), "+f"(c2), "+f"(c3)
                 : "r"(a0), "r"(a1), "r"(a2), "r"(a3), "r"(b0), "r"(b1));
}

// ---------------- pre-pass (unchanged) ---------------------------------------
__global__ void __launch_bounds__(256)
prepass_kernel(const float* __restrict__ q, const float* __restrict__ k)
{
    int gw = (blockIdx.x * 256 + threadIdx.x) >> 5;
    int lane = threadIdx.x & 31;
    if (gw < 64 * 128 * 2 * 4) {
        int ks = gw & 3, sp = (gw >> 2) & 1, blk = (gw >> 3) & 127, bh = gw >> 10;
        int r0 = blk * 16 + (lane >> 2);
        int kb = ks * 16 + (lane & 3) * 2;
        const float* qb = q + ((size_t)bh * Sc) * Dc;
        float2 p00 = *(const float2*)(qb + (size_t)r0 * Dc + kb);
        float2 p10 = *(const float2*)(qb + (size_t)(r0 + 8) * Dc + kb);
        float2 p01 = *(const float2*)(qb + (size_t)r0 * Dc + kb + 8);
        float2 p11 = *(const float2*)(qb + (size_t)(r0 + 8) * Dc + kb + 8);
        uint4 o;
        o.x = pk_split(p00.x * 8.f, p00.y * 8.f, sp);
        o.y = pk_split(p10.x * 8.f, p10.y * 8.f, sp);
        o.z = pk_split(p01.x * 8.f, p01.y * 8.f, sp);
        o.w = pk_split(p11.x * 8.f, p11.y * 8.f, sp);
        g_qfrag[(size_t)gw * 32 + lane] = o;
    } else {
        int w2 = gw - 64 * 128 * 2 * 4;
        int kp = w2 & 1, sp = (w2 >> 1) & 1, cbg = (w2 >> 2) & 255, bh = w2 >> 10;
        int n = cbg * 8 + (lane >> 2);
        const float* kr = k + ((size_t)bh * Sc + n) * Dc;
        uint4 o;
        int k0 = (kp * 2) * 16 + (lane & 3) * 2;
        o.x = pk_split(kr[k0], kr[k0 + 1], sp);
        o.y = pk_split(kr[k0 + 8], kr[k0 + 9], sp);
        int k1 = (kp * 2 + 1) * 16 + (lane & 3) * 2;
        o.z = pk_split(kr[k1], kr[k1 + 1], sp);
        o.w = pk_split(kr[k1 + 8], kr[k1 + 9], sp);
        g_kfrag[(size_t)w2 * 32 + lane] = o;
    }
}

// ---------------- main attention kernel (dual-chain MMA ILP) ----------------
__global__ void __launch_bounds__(256, 2)
attn_main(const float* __restrict__ gv, float* __restrict__ gout)
{
    __shared__ uint4 sK4[2048];   // 32 KB: one K-frag tile
    const int tid = threadIdx.x, w = tid >> 5, lane = tid & 31;
    const uint32_t bh = blockIdx.y;
    const int q0 = blockIdx.x * 128;
    const int blk = blockIdx.x * 8 + w;

    uint4 A[2][4];
    {
        const uint4* qf = g_qfrag + ((size_t)(bh * 128 + blk) * 2) * 4 * 32;
#pragma unroll
        for (int sp = 0; sp < 2; ++sp)
#pragma unroll
            for (int ks = 0; ks < 4; ++ks)
                A[sp][ks] = qf[(sp * 4 + ks) * 32 + lane];
    }

    float O[2][16];
#pragma unroll
    for (int r = 0; r < 2; ++r)
#pragma unroll
        for (int c = 0; c < 16; ++c) O[r][c] = 0.f;
    float m0 = -1e30f, m1 = -1e30f, l0 = 0.f, l1 = 0.f;

    const uint32_t gq0 = (uint32_t)(q0 + w * 16 + (lane >> 2));
    const float* vb = gv + (size_t)bh * Sc * Dc;

    for (int kt = 0; kt < 16; ++kt) {
        __syncthreads();
        {
            const uint4* kf = g_kfrag + (size_t)(bh * 16 + kt) * 2048;
#pragma unroll
            for (int i = 0; i < 8; ++i)
                sK4[tid + 256 * i] = kf[tid + 256 * i];
        }
        __syncthreads();

#pragma unroll 1
        for (int cb = 0; cb < 16; ++cb) {
            uint4 B[2][2];
#pragma unroll
            for (int sb = 0; sb < 2; ++sb)
#pragma unroll
                for (int kp = 0; kp < 2; ++kp)
                    B[sb][kp] = sK4[((cb * 2 + sb) * 2 + kp) * 32 + lane];

            // ---- dual independent chains: h = QhKh (4-deep), x = QlKh+QhKl (8-deep)
            float h0 = 0.f, h1 = 0.f, h2 = 0.f, h3 = 0.f;
            float x0 = 0.f, x1 = 0.f, x2 = 0.f, x3 = 0.f;
#pragma unroll
            for (int ks = 0; ks < 4; ++ks) {
                uint32_t hb0 = (ks & 1) ? B[0][ks >> 1].z : B[0][ks >> 1].x;
                uint32_t hb1 = (ks & 1) ? B[0][ks >> 1].w : B[0][ks >> 1].y;
                uint32_t lb0 = (ks & 1) ? B[1][ks >> 1].z : B[1][ks >> 1].x;
                uint32_t lb1 = (ks & 1) ? B[1][ks >> 1].w : B[1][ks >> 1].y;
                // interleave: x-step, h-step, x-step  (chains independent)
                mma16816(x0, x1, x2, x3,
                         A[1][ks].x, A[1][ks].y, A[1][ks].z, A[1][ks].w, hb0, hb1);
                mma16816(h0, h1, h2, h3,
                         A[0][ks].x, A[0][ks].y, A[0][ks].z, A[0][ks].w, hb0, hb1);
                mma16816(x0, x1, x2, x3,
                         A[0][ks].x, A[0][ks].y, A[0][ks].z, A[0][ks].w, lb0, lb1);
            }
            float c0 = h0 + x0, c1 = h1 + x1, c2 = h2 + x2, c3 = h3 + x3;

            // ---- cheap combined gate ----
            float bm = fmaxf(fmaxf(c0, c1), fmaxf(c2, c3));
            bm = fmaxf(bm, __shfl_xor_sync(0xffffffffu, bm, 1));
            bm = fmaxf(bm, __shfl_xor_sync(0xffffffffu, bm, 2));
            bool sig = bm > fminf(m0, m1) - 28.f;
            if (!__any_sync(0xffffffffu, sig)) continue;

            // ---- slow path (rare): precise row maxima, softmax, dropout ----
            float rm0 = fmaxf(c0, c1), rm1 = fmaxf(c2, c3);
            rm0 = fmaxf(rm0, __shfl_xor_sync(0xffffffffu, rm0, 1));
            rm0 = fmaxf(rm0, __shfl_xor_sync(0xffffffffu, rm0, 2));
            rm1 = fmaxf(rm1, __shfl_xor_sync(0xffffffffu, rm1, 1));
            rm1 = fmaxf(rm1, __shfl_xor_sync(0xffffffffu, rm1, 2));

            bool sv[4] = {false, false, false, false};
            float p10[4] = {0.f, 0.f, 0.f, 0.f};
            const int gk0 = kt * 128 + cb * 8 + (lane & 3) * 2;

            if (rm0 > m0 - 28.f) {
                float mn = fmaxf(m0, rm0);
                if (mn > m0) {
                    float al = __expf(m0 - mn);
                    l0 *= al;
#pragma unroll
                    for (int c = 0; c < 16; ++c) O[0][c] *= al;
                    m0 = mn;
                }
                float e0 = (c0 > mn - 28.f) ? __expf(c0 - mn) : 0.f;
                float e1 = (c1 > mn - 28.f) ? __expf(c1 - mn) : 0.f;
                l0 += e0 + e1;
                if (e0 > 1e-12f && keep_mask(bh, gq0, gk0))     { sv[0] = true; p10[0] = e0 * 10.f; }
                if (e1 > 1e-12f && keep_mask(bh, gq0, gk0 + 1)) { sv[1] = true; p10[1] = e1 * 10.f; }
            }
            if (rm1 > m1 - 28.f) {
                float mn = fmaxf(m1, rm1);
                if (mn > m1) {
                    float al = __expf(m1 - mn);
                    l1 *= al;
#pragma unroll
                    for (int c = 0; c < 16; ++c) O[1][c] *= al;
                    m1 = mn;
                }
                float e2 = (c2 > mn - 28.f) ? __expf(c2 - mn) : 0.f;
                float e3 = (c3 > mn - 28.f) ? __expf(c3 - mn) : 0.f;
                l1 += e2 + e3;
                if (e2 > 1e-12f && keep_mask(bh, gq0 + 8, gk0))     { sv[2] = true; p10[2] = e2 * 10.f; }
                if (e3 > 1e-12f && keep_mask(bh, gq0 + 8, gk0 + 1)) { sv[3] = true; p10[3] = e3 * 10.f; }
            }

            if (__ballot_sync(0xffffffffu, sv[0] | sv[1] | sv[2] | sv[3])) {
#pragma unroll
                for (int pos = 0; pos < 4; ++pos) {
                    unsigned mk = __ballot_sync(0xffffffffu, sv[pos]);
                    while (mk) {
                        int src = __ffs(mk) - 1;
                        mk &= mk - 1;
                        int gkb  = __shfl_sync(0xffffffffu, gk0 + (pos & 1), src);
                        float pb = __shfl_sync(0xffffffffu, p10[pos], src);
                        if ((lane >> 2) == (src >> 2)) {
                            const float* vc = vb + (size_t)gkb * Dc + (lane & 3) * 16;
                            float* Or = O[pos >> 1];
#pragma unroll
                            for (int c = 0; c < 4; ++c) {
                                float4 vv = *(const float4*)(vc + 4 * c);
                                Or[4 * c + 0] = fmaf(pb, vv.x, Or[4 * c + 0]);
                                Or[4 * c + 1] = fmaf(pb, vv.y, Or[4 * c + 1]);
                                Or[4 * c + 2] = fmaf(pb, vv.z, Or[4 * c + 2]);
                                Or[4 * c + 3] = fmaf(pb, vv.w, Or[4 * c + 3]);
                            }
                        }
                    }
                }
            }
        }
    }

    // ---- epilogue ----
    l0 += __shfl_xor_sync(0xffffffffu, l0, 1);
    l0 += __shfl_xor_sync(0xffffffffu, l0, 2);
    l1 += __shfl_xor_sync(0xffffffffu, l1, 1);
    l1 += __shfl_xor_sync(0xffffffffu, l1, 2);
    float il0 = 1.0f / l0, il1 = 1.0f / l1;

    const int gr0 = q0 + w * 16 + (lane >> 2);
    float* o0 = gout + ((size_t)bh * Sc + gr0) * Dc + (lane & 3) * 16;
    float* o1 = gout + ((size_t)bh * Sc + gr0 + 8) * Dc + (lane & 3) * 16;
#pragma unroll
    for (int c = 0; c < 4; ++c) {
        *(float4*)(o0 + 4 * c) = make_float4(O[0][4*c] * il0, O[0][4*c+1] * il0,
                                             O[0][4*c+2] * il0, O[0][4*c+3] * il0);
        *(float4*)(o1 + 4 * c) = make_float4(O[1][4*c] * il1, O[1][4*c+1] * il1,
                                             O[1][4*c+2] * il1, O[1][4*c+3] * il1);
    }
}

extern "C" void kernel_launch(void* const* d_in, const int* in_sizes, int n_in,
                              void* d_out, int out_size)
{
    (void)in_sizes; (void)n_in; (void)out_size;
    const float* q = (const float*)d_in[0];
    const float* k = (const float*)d_in[1];
    const float* v = (const float*)d_in[2];
    float* o = (float*)d_out;

    prepass_kernel<<<16384, 256>>>(q, k);
    dim3 grid(Sc / 128, 64);
    attn_main<<<grid, 256>>>(v, o);
}